// round 9
// baseline (speedup 1.0000x reference)
#include <cuda_runtime.h>
#include <cuda_fp16.h>
#include <cstdint>

// Problem constants
#define N_ROWS   32768
#define D_DIM    512
#define C_BOOKS  64
#define K_CODES  16
#define M_OUT    128
#define NODES    15

// Scratch
__device__ __align__(16) uint32_t g_codes[N_ROWS * 8];               // 4-bit codes
__device__ __align__(16) __half   g_Lf16[M_OUT * C_BOOKS * K_CODES]; // L fp16 [m][1024]

// ---------------------------------------------------------------------------
// PTX helpers (sm_103 baseline — harness ptxas targets sm_103, no tcgen05)
// ---------------------------------------------------------------------------
__device__ __forceinline__ uint32_t smem_u32(const void* p) {
    uint32_t a;
    asm("{ .reg .u64 t; cvta.to.shared.u64 t, %1; cvt.u32.u64 %0, t; }" : "=r"(a) : "l"(p));
    return a;
}
__device__ __forceinline__ void cp16(uint32_t dst, const void* src) {
    asm volatile("cp.async.cg.shared.global [%0], [%1], 16;" :: "r"(dst), "l"(src) : "memory");
}
#define CP_COMMIT() asm volatile("cp.async.commit_group;" ::: "memory")
#define CP_WAIT(n)  asm volatile("cp.async.wait_group %0;" :: "n"(n) : "memory")

__device__ __forceinline__ void ldsm4(uint32_t& r0, uint32_t& r1, uint32_t& r2,
                                      uint32_t& r3, uint32_t addr) {
    asm volatile("ldmatrix.sync.aligned.m8n8.x4.shared.b16 {%0,%1,%2,%3}, [%4];"
                 : "=r"(r0), "=r"(r1), "=r"(r2), "=r"(r3) : "r"(addr));
}
__device__ __forceinline__ void mma16816(float* c, uint32_t a0, uint32_t a1,
                                         uint32_t a2, uint32_t a3,
                                         uint32_t b0, uint32_t b1) {
    asm volatile("mma.sync.aligned.m16n8k16.row.col.f32.f16.f16.f32 "
                 "{%0,%1,%2,%3}, {%4,%5,%6,%7}, {%8,%9}, {%0,%1,%2,%3};"
                 : "+f"(c[0]), "+f"(c[1]), "+f"(c[2]), "+f"(c[3])
                 : "r"(a0), "r"(a1), "r"(a2), "r"(a3), "r"(b0), "r"(b1));
}

// ---------------------------------------------------------------------------
// Kernel 1: encode (16 rows/CTA, 256 threads) + fused L->fp16 convert.
// ---------------------------------------------------------------------------
#define ENC_ROWS    16
#define ENC_THREADS 256
#define ROW_PAD     516

__global__ __launch_bounds__(ENC_THREADS)
void encode_kernel(const float* __restrict__ I,
                   const float* __restrict__ T,
                   const int*   __restrict__ dims,
                   const float* __restrict__ L)
{
    extern __shared__ float sm[];
    float* Ir = sm;
    float* Ts = sm + ENC_ROWS * ROW_PAD;
    int*   ds = (int*)(Ts + 960);

    const int tid = threadIdx.x;
    const int nb  = blockIdx.x * ENC_ROWS;
    const uint32_t sbase = smem_u32(sm);

    // cp.async staging of 16 rows (2048 x 16B)
    const char* src = (const char*)(I + (size_t)nb * D_DIM);
    #pragma unroll
    for (int i = 0; i < 8; i++) {
        int q = tid + ENC_THREADS * i;
        int r = q >> 7;
        int j = q & 127;
        cp16(sbase + (uint32_t)(r * (ROW_PAD * 4) + j * 16),
             src + (size_t)r * (D_DIM * 4) + j * 16);
    }
    CP_COMMIT();

    // Fused convert: first 128 CTAs each convert 256 float4 of L -> g_Lf16
    if (blockIdx.x < 128) {
        int q = blockIdx.x * 256 + tid;
        float4 v = ((const float4*)L)[q];
        ((__half2*)g_Lf16)[q * 2]     = __floats2half2_rn(v.x, v.y);
        ((__half2*)g_Lf16)[q * 2 + 1] = __floats2half2_rn(v.z, v.w);
    }

    for (int i = tid; i < 960; i += ENC_THREADS) Ts[i] = T[i];
    ds[tid] = dims[tid];

    CP_WAIT(0);
    __syncthreads();

    const int r  = tid >> 4;
    const int cg = tid & 15;
    const float* row = Ir + r * ROW_PAD;

    uint32_t pack = 0;
    #pragma unroll
    for (int j = 0; j < 4; j++) {
        const int c = cg * 4 + j;
        const int*   dp = ds + c * 4;
        const float* tp = Ts + c * NODES;
        const float v0 = row[dp[0]];
        const float v1 = row[dp[1]];
        const float v2 = row[dp[2]];
        const float v3 = row[dp[3]];
        int p;
        p = (v0 > tp[0]) ? 1 : 0;
        p = (p << 1) | ((v1 > tp[1 + p]) ? 1 : 0);
        p = (p << 1) | ((v2 > tp[3 + p]) ? 1 : 0);
        p = (p << 1) | ((v3 > tp[7 + p]) ? 1 : 0);
        pack |= ((uint32_t)p) << (4 * j);
    }
    ((uint16_t*)g_codes)[(size_t)(nb + r) * 16 + cg] = (uint16_t)pack;
}

// ---------------------------------------------------------------------------
// Kernel 2: tensor aggregation (mma.sync m16n8k16).
// CTA: 128 rows x 128 m, 256 threads = 8 warps as 4(n) x 2(m);
// warp = 32 rows x 64 m. Warp-staggered k-block order ((kb + wid) & 7)
// de-phases LDSM bursts; B fragments software-pipelined in pairs.
// B chunk double-buffered via cp.async from g_Lf16, 1 sync/chunk.
// A one-hot synthesized in registers from 4-bit codes.
// ---------------------------------------------------------------------------
#define AGG_THREADS 256
#define NTILE       128
#define BROW        272                         // 256B data + 16B pad per m-row
#define BTILE_B     (128 * BROW)                // 34816
#define SM_BUF      4096
#define SM_AGG      (SM_BUF + 2 * BTILE_B)      // 73728

__global__ __launch_bounds__(AGG_THREADS, 2)
void agg_kernel(float* __restrict__ out)
{
    extern __shared__ __align__(16) char smem[];
    const uint32_t sb = smem_u32(smem);
    const int tid  = threadIdx.x;
    const int wid  = tid >> 5;
    const int lane = tid & 31;
    const int g    = lane >> 2;     // 0..7
    const int tg   = lane & 3;      // 0..3
    const int n0   = blockIdx.x * NTILE;

    // Stage codes: 128 rows * 32B = 256 uint4
    {
        const uint4* srcc = (const uint4*)(g_codes + (size_t)n0 * 8);
        ((uint4*)smem)[tid] = srcc[tid];
    }

    // ldmatrix per-lane constant offset (validated layout)
    const int t = lane >> 3;
    const uint32_t lane_m   = (uint32_t)(((t >> 1) * 8) + (lane & 7));
    const uint32_t lane_off = lane_m * BROW + (uint32_t)((t & 1) * 16);

    const int rbase = (wid & 3) * 32;    // warp rows within CTA
    const int mwarp = (wid >> 2) * 64;   // warp m within CTA

    // stage chunk 'c' (128 m x 128 k) into buffer buf
    const char* srcL = (const char*)g_Lf16;
    #define STAGE(c, buf)                                                        \
        do {                                                                     \
            const uint32_t bdst = sb + SM_BUF + (buf) * BTILE_B;                 \
            const char* s = srcL + (c) * 256;                                    \
            _Pragma("unroll")                                                    \
            for (int i = 0; i < 8; i++) {                                        \
                int q = tid + AGG_THREADS * i;                                   \
                int m = q >> 4, seg = q & 15;                                    \
                cp16(bdst + (uint32_t)(m * BROW + seg * 16),                     \
                     s + (size_t)m * 2048 + seg * 16);                           \
            }                                                                    \
            CP_COMMIT();                                                         \
        } while (0)

    STAGE(0, 0);

    float acc[2][8][4];
    #pragma unroll
    for (int rt = 0; rt < 2; rt++)
        #pragma unroll
        for (int nb = 0; nb < 8; nb++)
            #pragma unroll
            for (int i = 0; i < 4; i++) acc[rt][nb][i] = 0.f;

    const uint32_t* cs = (const uint32_t*)smem;

    #pragma unroll 1
    for (int ch = 0; ch < 8; ch++) {
        CP_WAIT(0);
        __syncthreads();
        if (ch < 7) { STAGE(ch + 1, (ch + 1) & 1); }   // overlaps with consume

        const uint32_t bbase = sb + SM_BUF + (ch & 1) * BTILE_B
                             + (uint32_t)mwarp * BROW + lane_off;

        // code words: 2 row-tiles x (row g, row g+8)
        uint32_t wlo[2], whi[2];
        #pragma unroll
        for (int rt = 0; rt < 2; rt++) {
            wlo[rt] = cs[(rbase + 16 * rt + g)     * 8 + ch];
            whi[rt] = cs[(rbase + 16 * rt + g + 8) * 8 + ch];
        }

        // Warp-staggered k-block order + pipelined fragment pairs.
        int kbl = wid & 7;
        uint32_t ba[2][4], bb[2][4];
        ldsm4(ba[0][0], ba[0][1], ba[0][2], ba[0][3],
              bbase + (uint32_t)(kbl * 32));
        ldsm4(ba[1][0], ba[1][1], ba[1][2], ba[1][3],
              bbase + (uint32_t)(kbl * 32) + (uint32_t)(16 * BROW));

        #pragma unroll
        for (int kb = 0; kb < 8; kb++) {
            const uint32_t koff = (uint32_t)kbl * 32;
            // second pair of fragments for current kbl (m +32..63)
            ldsm4(bb[0][0], bb[0][1], bb[0][2], bb[0][3],
                  bbase + koff + (uint32_t)(2 * 16 * BROW));
            ldsm4(bb[1][0], bb[1][1], bb[1][2], bb[1][3],
                  bbase + koff + (uint32_t)(3 * 16 * BROW));

            // A one-hot fragments for this kbl
            const uint32_t sh = 4u * (uint32_t)kbl;
            uint32_t A[2][4];
            #pragma unroll
            for (int rt = 0; rt < 2; rt++) {
                const uint32_t klo = (wlo[rt] >> sh) & 15u;
                const uint32_t khi = (whi[rt] >> sh) & 15u;
                const uint32_t hlo = 0x3C00u << ((klo & 1u) << 4);
                const uint32_t hhi = 0x3C00u << ((khi & 1u) << 4);
                const uint32_t slo = klo >> 1, shi = khi >> 1;
                A[rt][0] = (slo == (uint32_t)tg)     ? hlo : 0u;
                A[rt][1] = (shi == (uint32_t)tg)     ? hhi : 0u;
                A[rt][2] = (slo == (uint32_t)tg + 4) ? hlo : 0u;
                A[rt][3] = (shi == (uint32_t)tg + 4) ? hhi : 0u;
            }

            // MMAs on first pair (nb 0..3)
            #pragma unroll
            for (int rt = 0; rt < 2; rt++) {
                mma16816(acc[rt][0], A[rt][0], A[rt][1], A[rt][2], A[rt][3],
                         ba[0][0], ba[0][1]);
                mma16816(acc[rt][1], A[rt][0], A[rt][1], A[rt][2], A[rt][3],
                         ba[0][2], ba[0][3]);
                mma16816(acc[rt][2], A[rt][0], A[rt][1], A[rt][2], A[rt][3],
                         ba[1][0], ba[1][1]);
                mma16816(acc[rt][3], A[rt][0], A[rt][1], A[rt][2], A[rt][3],
                         ba[1][2], ba[1][3]);
            }

            // prefetch first pair of NEXT kbl
            const int kbln = (kb + 1 + wid) & 7;
            if (kb < 7) {
                ldsm4(ba[0][0], ba[0][1], ba[0][2], ba[0][3],
                      bbase + (uint32_t)(kbln * 32));
                ldsm4(ba[1][0], ba[1][1], ba[1][2], ba[1][3],
                      bbase + (uint32_t)(kbln * 32) + (uint32_t)(16 * BROW));
            }

            // MMAs on second pair (nb 4..7)
            #pragma unroll
            for (int rt = 0; rt < 2; rt++) {
                mma16816(acc[rt][4], A[rt][0], A[rt][1], A[rt][2], A[rt][3],
                         bb[0][0], bb[0][1]);
                mma16816(acc[rt][5], A[rt][0], A[rt][1], A[rt][2], A[rt][3],
                         bb[0][2], bb[0][3]);
                mma16816(acc[rt][6], A[rt][0], A[rt][1], A[rt][2], A[rt][3],
                         bb[1][0], bb[1][1]);
                mma16816(acc[rt][7], A[rt][0], A[rt][1], A[rt][2], A[rt][3],
                         bb[1][2], bb[1][3]);
            }
            kbl = kbln;
        }
    }

    // Epilogue: STG.64 pairs
    #pragma unroll
    for (int rt = 0; rt < 2; rt++) {
        const int rowA = n0 + rbase + 16 * rt + g;
        #pragma unroll
        for (int nb = 0; nb < 8; nb++) {
            float2 lo = make_float2(acc[rt][nb][0], acc[rt][nb][1]);
            float2 hi = make_float2(acc[rt][nb][2], acc[rt][nb][3]);
            *(float2*)(out + (size_t)rowA * M_OUT + mwarp + nb * 8 + tg * 2)       = lo;
            *(float2*)(out + (size_t)(rowA + 8) * M_OUT + mwarp + nb * 8 + tg * 2) = hi;
        }
    }
    #undef STAGE
}

// ---------------------------------------------------------------------------
extern "C" void kernel_launch(void* const* d_in, const int* in_sizes, int n_in,
                              void* d_out, int out_size)
{
    (void)in_sizes; (void)n_in; (void)out_size;
    const float* I    = (const float*)d_in[0];
    const float* T    = (const float*)d_in[1];
    const float* L    = (const float*)d_in[2];
    const int*   dims = (const int*)d_in[5];
    float* out = (float*)d_out;

    const int encSmem = (ENC_ROWS * ROW_PAD + 960 + 256) * 4;  // 37888
    cudaFuncSetAttribute(encode_kernel, cudaFuncAttributeMaxDynamicSharedMemorySize, encSmem);
    cudaFuncSetAttribute(agg_kernel,    cudaFuncAttributeMaxDynamicSharedMemorySize, SM_AGG);

    encode_kernel<<<N_ROWS / ENC_ROWS, ENC_THREADS, encSmem>>>(I, T, dims, L);
    agg_kernel<<<N_ROWS / NTILE, AGG_THREADS, SM_AGG>>>(out);
}

// round 10
// speedup vs baseline: 1.0842x; 1.0842x over previous
#include <cuda_runtime.h>
#include <cuda_fp16.h>
#include <cstdint>

// Problem constants
#define N_ROWS   32768
#define D_DIM    512
#define C_BOOKS  64
#define K_CODES  16
#define M_OUT    128
#define NODES    15

// Scratch
__device__ __align__(16) uint32_t g_codes[N_ROWS * 8];               // 4-bit codes
__device__ __align__(16) __half   g_Lf16[M_OUT * C_BOOKS * K_CODES]; // L fp16 [m][1024]

// ---------------------------------------------------------------------------
// PTX helpers (sm_103 baseline — harness ptxas targets sm_103, no tcgen05)
// ---------------------------------------------------------------------------
__device__ __forceinline__ uint32_t smem_u32(const void* p) {
    uint32_t a;
    asm("{ .reg .u64 t; cvta.to.shared.u64 t, %1; cvt.u32.u64 %0, t; }" : "=r"(a) : "l"(p));
    return a;
}
__device__ __forceinline__ void cp16(uint32_t dst, const void* src) {
    asm volatile("cp.async.cg.shared.global [%0], [%1], 16;" :: "r"(dst), "l"(src) : "memory");
}
#define CP_COMMIT() asm volatile("cp.async.commit_group;" ::: "memory")
#define CP_WAIT(n)  asm volatile("cp.async.wait_group %0;" :: "n"(n) : "memory")

__device__ __forceinline__ void ldsm4(uint32_t& r0, uint32_t& r1, uint32_t& r2,
                                      uint32_t& r3, uint32_t addr) {
    asm volatile("ldmatrix.sync.aligned.m8n8.x4.shared.b16 {%0,%1,%2,%3}, [%4];"
                 : "=r"(r0), "=r"(r1), "=r"(r2), "=r"(r3) : "r"(addr));
}
__device__ __forceinline__ void mma16816(float* c, uint32_t a0, uint32_t a1,
                                         uint32_t a2, uint32_t a3,
                                         uint32_t b0, uint32_t b1) {
    asm volatile("mma.sync.aligned.m16n8k16.row.col.f32.f16.f16.f32 "
                 "{%0,%1,%2,%3}, {%4,%5,%6,%7}, {%8,%9}, {%0,%1,%2,%3};"
                 : "+f"(c[0]), "+f"(c[1]), "+f"(c[2]), "+f"(c[3])
                 : "r"(a0), "r"(a1), "r"(a2), "r"(a3), "r"(b0), "r"(b1));
}

// ---------------------------------------------------------------------------
// Kernel 1: encode (16 rows/CTA, 256 threads) + fused L->fp16 convert.
// ---------------------------------------------------------------------------
#define ENC_ROWS    16
#define ENC_THREADS 256
#define ROW_PAD     516

__global__ __launch_bounds__(ENC_THREADS)
void encode_kernel(const float* __restrict__ I,
                   const float* __restrict__ T,
                   const int*   __restrict__ dims,
                   const float* __restrict__ L)
{
    extern __shared__ float sm[];
    float* Ir = sm;
    float* Ts = sm + ENC_ROWS * ROW_PAD;
    int*   ds = (int*)(Ts + 960);

    const int tid = threadIdx.x;
    const int nb  = blockIdx.x * ENC_ROWS;
    const uint32_t sbase = smem_u32(sm);

    // cp.async staging of 16 rows (2048 x 16B)
    const char* src = (const char*)(I + (size_t)nb * D_DIM);
    #pragma unroll
    for (int i = 0; i < 8; i++) {
        int q = tid + ENC_THREADS * i;
        int r = q >> 7;
        int j = q & 127;
        cp16(sbase + (uint32_t)(r * (ROW_PAD * 4) + j * 16),
             src + (size_t)r * (D_DIM * 4) + j * 16);
    }
    CP_COMMIT();

    // Fused convert: first 128 CTAs each convert 256 float4 of L -> g_Lf16
    if (blockIdx.x < 128) {
        int q = blockIdx.x * 256 + tid;
        float4 v = ((const float4*)L)[q];
        ((__half2*)g_Lf16)[q * 2]     = __floats2half2_rn(v.x, v.y);
        ((__half2*)g_Lf16)[q * 2 + 1] = __floats2half2_rn(v.z, v.w);
    }

    for (int i = tid; i < 960; i += ENC_THREADS) Ts[i] = T[i];
    ds[tid] = dims[tid];

    CP_WAIT(0);
    __syncthreads();

    const int r  = tid >> 4;
    const int cg = tid & 15;
    const float* row = Ir + r * ROW_PAD;

    uint32_t pack = 0;
    #pragma unroll
    for (int j = 0; j < 4; j++) {
        const int c = cg * 4 + j;
        const int*   dp = ds + c * 4;
        const float* tp = Ts + c * NODES;
        const float v0 = row[dp[0]];
        const float v1 = row[dp[1]];
        const float v2 = row[dp[2]];
        const float v3 = row[dp[3]];
        int p;
        p = (v0 > tp[0]) ? 1 : 0;
        p = (p << 1) | ((v1 > tp[1 + p]) ? 1 : 0);
        p = (p << 1) | ((v2 > tp[3 + p]) ? 1 : 0);
        p = (p << 1) | ((v3 > tp[7 + p]) ? 1 : 0);
        pack |= ((uint32_t)p) << (4 * j);
    }
    ((uint16_t*)g_codes)[(size_t)(nb + r) * 16 + cg] = (uint16_t)pack;
}

// ---------------------------------------------------------------------------
// Kernel 2: tensor aggregation (mma.sync m16n8k16).
// Tile: 128 rows x 64 m per CTA, grid (256, 2). 8 warps: warp = 16n x 64m
// -> acc[8][4] = 32 regs/thread; __launch_bounds__(256,3) -> 3 CTAs/SM,
// 24 warps (37.5% occ). Synthesis amortized over 8 MMAs/kbl (ALU/MMA = 1.5).
// B chunk (64m x 128k fp16) double-buffered via cp.async, 1 sync/chunk.
// ---------------------------------------------------------------------------
#define AGG_THREADS 256
#define NTILE       128
#define MTILE       64
#define BROW        272                         // 256B data + 16B pad per m-row
#define BTILE_B     (MTILE * BROW)              // 17408
#define SM_BUF      4096
#define SM_AGG      (SM_BUF + 2 * BTILE_B)      // 38912 -> 3 CTAs/SM

__global__ __launch_bounds__(AGG_THREADS, 3)
void agg_kernel(float* __restrict__ out)
{
    extern __shared__ __align__(16) char smem[];
    const uint32_t sb = smem_u32(smem);
    const int tid  = threadIdx.x;
    const int wid  = tid >> 5;
    const int lane = tid & 31;
    const int g    = lane >> 2;     // 0..7
    const int tg   = lane & 3;      // 0..3
    const int n0   = blockIdx.x * NTILE;
    const int mg0  = blockIdx.y * MTILE;

    // Stage codes: 128 rows * 32B = 256 uint4
    {
        const uint4* srcc = (const uint4*)(g_codes + (size_t)n0 * 8);
        ((uint4*)smem)[tid] = srcc[tid];
    }

    // ldmatrix per-lane constant offset (validated layout)
    const int t = lane >> 3;
    const uint32_t lane_m   = (uint32_t)(((t >> 1) * 8) + (lane & 7));
    const uint32_t lane_off = lane_m * BROW + (uint32_t)((t & 1) * 16);

    const int rbase = wid * 16;          // warp rows within CTA (16 each)

    // stage chunk 'c' (64 m x 128 k) into buffer buf: 1024 cp16 / 256 thr
    const char* srcL = (const char*)g_Lf16 + (size_t)mg0 * 2048;
    #define STAGE(c, buf)                                                        \
        do {                                                                     \
            const uint32_t bdst = sb + SM_BUF + (buf) * BTILE_B;                 \
            const char* s = srcL + (c) * 256;                                    \
            _Pragma("unroll")                                                    \
            for (int i = 0; i < 4; i++) {                                        \
                int q = tid + AGG_THREADS * i;                                   \
                int m = q >> 4, seg = q & 15;                                    \
                cp16(bdst + (uint32_t)(m * BROW + seg * 16),                     \
                     s + (size_t)m * 2048 + seg * 16);                           \
            }                                                                    \
            CP_COMMIT();                                                         \
        } while (0)

    STAGE(0, 0);

    float acc[8][4];
    #pragma unroll
    for (int nb = 0; nb < 8; nb++)
        #pragma unroll
        for (int i = 0; i < 4; i++) acc[nb][i] = 0.f;

    const uint32_t* cs = (const uint32_t*)smem;

    #pragma unroll 1
    for (int ch = 0; ch < 8; ch++) {
        CP_WAIT(0);
        __syncthreads();
        if (ch < 7) { STAGE(ch + 1, (ch + 1) & 1); }   // overlaps with consume

        const uint32_t bbase = sb + SM_BUF + (ch & 1) * BTILE_B + lane_off;

        const uint32_t wlo = cs[(rbase + g)     * 8 + ch];
        const uint32_t whi = cs[(rbase + g + 8) * 8 + ch];

        #pragma unroll
        for (int kbl = 0; kbl < 8; kbl++) {
            // B fragments: 64 m = four 16-m ldmatrix.x4
            uint32_t b[4][4];
            #pragma unroll
            for (int p = 0; p < 4; p++) {
                ldsm4(b[p][0], b[p][1], b[p][2], b[p][3],
                      bbase + (uint32_t)(kbl * 32) + (uint32_t)(p * 16 * BROW));
            }
            // A one-hot fragments (row g from wlo, row g+8 from whi)
            const uint32_t klo = (wlo >> (4 * kbl)) & 15u;
            const uint32_t khi = (whi >> (4 * kbl)) & 15u;
            const uint32_t hlo = 0x3C00u << ((klo & 1u) << 4);
            const uint32_t hhi = 0x3C00u << ((khi & 1u) << 4);
            const uint32_t slo = klo >> 1, shi = khi >> 1;
            const uint32_t A0 = (slo == (uint32_t)tg)     ? hlo : 0u;
            const uint32_t A1 = (shi == (uint32_t)tg)     ? hhi : 0u;
            const uint32_t A2 = (slo == (uint32_t)tg + 4) ? hlo : 0u;
            const uint32_t A3 = (shi == (uint32_t)tg + 4) ? hhi : 0u;

            #pragma unroll
            for (int p = 0; p < 4; p++) {
                mma16816(acc[2 * p],     A0, A1, A2, A3, b[p][0], b[p][1]);
                mma16816(acc[2 * p + 1], A0, A1, A2, A3, b[p][2], b[p][3]);
            }
        }
    }

    // Epilogue: STG.64 pairs
    {
        const int rowA = n0 + rbase + g;
        #pragma unroll
        for (int nb = 0; nb < 8; nb++) {
            float2 lo = make_float2(acc[nb][0], acc[nb][1]);
            float2 hi = make_float2(acc[nb][2], acc[nb][3]);
            *(float2*)(out + (size_t)rowA * M_OUT + mg0 + nb * 8 + tg * 2)       = lo;
            *(float2*)(out + (size_t)(rowA + 8) * M_OUT + mg0 + nb * 8 + tg * 2) = hi;
        }
    }
    #undef STAGE
}

// ---------------------------------------------------------------------------
extern "C" void kernel_launch(void* const* d_in, const int* in_sizes, int n_in,
                              void* d_out, int out_size)
{
    (void)in_sizes; (void)n_in; (void)out_size;
    const float* I    = (const float*)d_in[0];
    const float* T    = (const float*)d_in[1];
    const float* L    = (const float*)d_in[2];
    const int*   dims = (const int*)d_in[5];
    float* out = (float*)d_out;

    const int encSmem = (ENC_ROWS * ROW_PAD + 960 + 256) * 4;  // 37888
    cudaFuncSetAttribute(encode_kernel, cudaFuncAttributeMaxDynamicSharedMemorySize, encSmem);
    cudaFuncSetAttribute(agg_kernel,    cudaFuncAttributeMaxDynamicSharedMemorySize, SM_AGG);

    encode_kernel<<<N_ROWS / ENC_ROWS, ENC_THREADS, encSmem>>>(I, T, dims, L);
    agg_kernel<<<dim3(N_ROWS / NTILE, M_OUT / MTILE), AGG_THREADS, SM_AGG>>>(out);
}